// round 5
// baseline (speedup 1.0000x reference)
#include <cuda_runtime.h>
#include <cstdint>
#include <math.h>

// ---------------------------------------------------------------------------
// SoftEmbRescore (sm_100 base ISA -- tcgen05 NOT available under this build):
//   G    = emb @ emb^T        (tf32 mma.sync, 1024x1024, tf32-rounded store)
//   dots = x @ G              (tf32 mma.sync, 256x256x16 CTA tiles, 64x64/warp)
//   out[i,j] = dots[i,j] / max(s_i * e_j, 1e-8)
//     e_j = sqrt(G[j,j]);  s_i = sqrt(sum_j dots[i,j]*x[i,j])   (row-local)
// One 65536x1024x1024 GEMM instead of the reference's two fp32 GEMMs.
// ---------------------------------------------------------------------------

namespace {
constexpr int MDIM = 65536;
constexpr int NDIM = 1024;
constexpr int KDIM = 1024;

// ---- main GEMM tiling ----
constexpr int BM = 256;
constexpr int BN = 256;
constexpr int BK = 16;
constexpr int LDSS = BK + 4;                    // 20-float rows: conflict-free frags
constexpr int NTHREADS = 512;
constexpr int NSTAGE = 4;
constexpr int NT = KDIM / BK;                   // 64
constexpr int STAGE_FLOATS = (BM + BN) * LDSS;  // 10240 floats = 40 KB
constexpr int SMEM_MAIN = NSTAGE * STAGE_FLOATS * 4;  // 163840 B (dynamic)

// ---- G-builder tiling (small, 64 CTAs) ----
constexpr int GBM = 128, GBN = 128, GBK = 16;
constexpr int GLDS = GBK + 4;
constexpr int GNT = KDIM / GBK;
constexpr int GSTAGE = (GBM + GBN) * GLDS;      // 5120 floats
}

__device__ __align__(16) float g_mat[(size_t)NDIM * NDIM];   // 4 MB (tf32-rounded)
__device__ __align__(16) float e_norm[NDIM];

// ============================ helpers ======================================

__device__ __forceinline__ uint32_t smem_u32(const void* p) {
    uint32_t a;
    asm("{ .reg .u64 t; cvta.to.shared.u64 t, %1; cvt.u32.u64 %0, t; }" : "=r"(a) : "l"(p));
    return a;
}
__device__ __forceinline__ uint32_t f2tf32(float f) {
    uint32_t r;
    asm("cvt.rna.tf32.f32 %0, %1;" : "=r"(r) : "f"(f));
    return r;
}
__device__ __forceinline__ void mma_tf32(float* d, const uint32_t* a, const uint32_t* b) {
    asm volatile(
        "mma.sync.aligned.m16n8k8.row.col.f32.tf32.tf32.f32 "
        "{%0,%1,%2,%3}, {%4,%5,%6,%7}, {%8,%9}, {%0,%1,%2,%3};"
        : "+f"(d[0]), "+f"(d[1]), "+f"(d[2]), "+f"(d[3])
        : "r"(a[0]), "r"(a[1]), "r"(a[2]), "r"(a[3]), "r"(b[0]), "r"(b[1]));
}

#define CP_ASYNC16(dst, src) \
    asm volatile("cp.async.cg.shared.global [%0], [%1], 16;" :: "r"(dst), "l"(src))
#define CP_COMMIT() asm volatile("cp.async.commit_group;")
#define CP_WAIT3()  asm volatile("cp.async.wait_group 3;")
#define CP_WAIT1()  asm volatile("cp.async.wait_group 1;")
#define CP_WAIT0()  asm volatile("cp.async.wait_group 0;")

// ============== kernel 1: G = emb @ emb^T (tf32-rounded store) =============

__global__ __launch_bounds__(256, 2)
void g_gemm_kernel(const float* __restrict__ A)
{
    __shared__ __align__(16) float smem[2 * GSTAGE];
    const int tid = threadIdx.x;
    const int m0 = blockIdx.y * GBM;
    const int n0 = blockIdx.x * GBN;

    auto load_stage = [&](int s, int kt) {
        const float* Ag = A + (size_t)m0 * KDIM + kt * GBK;
        const float* Bg = A + (size_t)n0 * KDIM + kt * GBK;
        float* Asm = smem + s * GSTAGE;
        float* Bsm = Asm + GBM * GLDS;
        #pragma unroll
        for (int i = 0; i < 2; ++i) {
            int chunk = tid + i * 256;
            int r = chunk >> 2;
            int c = (chunk & 3) * 4;
            CP_ASYNC16(smem_u32(Asm + r * GLDS + c), Ag + (size_t)r * KDIM + c);
            CP_ASYNC16(smem_u32(Bsm + r * GLDS + c), Bg + (size_t)r * KDIM + c);
        }
        CP_COMMIT();
    };

    const int warp = tid >> 5, lane = tid & 31;
    const int mb = (warp & 3) * 32, nb = (warp >> 2) * 64;
    const int grp = lane >> 2, tig = lane & 3;

    float d[2][8][4];
    #pragma unroll
    for (int mi = 0; mi < 2; ++mi)
        #pragma unroll
        for (int ni = 0; ni < 8; ++ni)
            #pragma unroll
            for (int r = 0; r < 4; ++r) d[mi][ni][r] = 0.f;

    load_stage(0, 0);
    for (int t = 0; t < GNT; ++t) {
        if (t + 1 < GNT) { load_stage((t + 1) & 1, t + 1); CP_WAIT1(); }
        else             { CP_WAIT0(); }
        __syncthreads();
        const float* Asm = smem + (t & 1) * GSTAGE;
        const float* Bsm = Asm + GBM * GLDS;
        #pragma unroll
        for (int kk = 0; kk < GBK; kk += 8) {
            uint32_t a[2][4];
            #pragma unroll
            for (int mi = 0; mi < 2; ++mi) {
                const float* p = Asm + (mb + mi * 16 + grp) * GLDS + kk + tig;
                a[mi][0] = f2tf32(p[0]);
                a[mi][1] = f2tf32(p[8 * GLDS]);
                a[mi][2] = f2tf32(p[4]);
                a[mi][3] = f2tf32(p[8 * GLDS + 4]);
            }
            uint32_t b[8][2];
            #pragma unroll
            for (int ni = 0; ni < 8; ++ni) {
                const float* p = Bsm + (nb + ni * 8 + grp) * GLDS + kk + tig;
                b[ni][0] = f2tf32(p[0]);
                b[ni][1] = f2tf32(p[4]);
            }
            #pragma unroll
            for (int mi = 0; mi < 2; ++mi)
                #pragma unroll
                for (int ni = 0; ni < 8; ++ni)
                    mma_tf32(d[mi][ni], a[mi], b[ni]);
        }
        __syncthreads();
    }
    #pragma unroll
    for (int mi = 0; mi < 2; ++mi) {
        #pragma unroll
        for (int ni = 0; ni < 8; ++ni) {
            int row = m0 + mb + mi * 16 + grp;
            int col = n0 + nb + ni * 8 + 2 * tig;
            g_mat[(size_t)row * NDIM + col]           = __uint_as_float(f2tf32(d[mi][ni][0]));
            g_mat[(size_t)row * NDIM + col + 1]       = __uint_as_float(f2tf32(d[mi][ni][1]));
            g_mat[(size_t)(row + 8) * NDIM + col]     = __uint_as_float(f2tf32(d[mi][ni][2]));
            g_mat[(size_t)(row + 8) * NDIM + col + 1] = __uint_as_float(f2tf32(d[mi][ni][3]));
        }
    }
}

__global__ void diag_norm_kernel() {
    int j = blockIdx.x * blockDim.x + threadIdx.x;
    if (j < NDIM) e_norm[j] = sqrtf(fmaxf(g_mat[(size_t)j * NDIM + j], 0.f));
}

// =========== kernel 2: dots = x @ G, 256x256 CTA tile, 64x64/warp ==========
// 4-stage cp.async pipeline. LDS:MMA ratio 1.0 (vs 1.5 at 32x64 warp tile).

__global__ __launch_bounds__(NTHREADS, 1)
void main_gemm_kernel(const float* __restrict__ x, float* __restrict__ out)
{
    extern __shared__ __align__(16) float smem[];
    const int tid = threadIdx.x;
    const int m0 = blockIdx.y * BM;
    const int n0 = blockIdx.x * BN;

    auto fill = [&](int kt) {
        float* S = smem + (kt & 3) * STAGE_FLOATS;
        const float* Ag = x + (size_t)m0 * KDIM + kt * BK;
        const float* Bg = g_mat + (size_t)n0 * KDIM + kt * BK;
        #pragma unroll
        for (int i = 0; i < 4; ++i) {
            int chunk = tid + i * NTHREADS;       // 0..2047
            int r = chunk >> 2;                   // 0..511
            int c = (chunk & 3) * 4;              // 0,4,8,12
            const float* src = (r < BM) ? (Ag + (size_t)r * KDIM + c)
                                        : (Bg + (size_t)(r - BM) * KDIM + c);
            CP_ASYNC16(smem_u32(S + r * LDSS + c), src);
        }
        CP_COMMIT();
    };

    const int warp = tid >> 5, lane = tid & 31;
    const int mb = (warp & 3) * 64;               // 4 warps along M
    const int nb = (warp >> 2) * 64;              // 4 warps along N
    const int grp = lane >> 2, tig = lane & 3;

    float d[4][8][4];
    #pragma unroll
    for (int mi = 0; mi < 4; ++mi)
        #pragma unroll
        for (int ni = 0; ni < 8; ++ni)
            #pragma unroll
            for (int r = 0; r < 4; ++r) d[mi][ni][r] = 0.f;

    // prologue: stages 0..2
    fill(0); fill(1); fill(2);

    for (int t = 0; t < NT; ++t) {
        if (t + 3 < NT) fill(t + 3);
        else            CP_COMMIT();              // keep group accounting fixed
        CP_WAIT3();                               // group t complete
        __syncthreads();                          // visibility across threads

        const float* Asm = smem + (t & 3) * STAGE_FLOATS;
        const float* Bsm = Asm + BM * LDSS;

        #pragma unroll
        for (int kk = 0; kk < BK; kk += 8) {
            uint32_t a[4][4];
            #pragma unroll
            for (int mi = 0; mi < 4; ++mi) {
                const float* p = Asm + (mb + mi * 16 + grp) * LDSS + kk + tig;
                a[mi][0] = f2tf32(p[0]);
                a[mi][1] = f2tf32(p[8 * LDSS]);
                a[mi][2] = f2tf32(p[4]);
                a[mi][3] = f2tf32(p[8 * LDSS + 4]);
            }
            uint32_t b[8][2];
            #pragma unroll
            for (int ni = 0; ni < 8; ++ni) {
                const float* p = Bsm + (nb + ni * 8 + grp) * LDSS + kk + tig;
                b[ni][0] = __float_as_uint(p[0]);   // g_mat pre-rounded to tf32
                b[ni][1] = __float_as_uint(p[4]);
            }
            #pragma unroll
            for (int mi = 0; mi < 4; ++mi)
                #pragma unroll
                for (int ni = 0; ni < 8; ++ni)
                    mma_tf32(d[mi][ni], a[mi], b[ni]);
        }
        __syncthreads();                          // all warps done reading buf t
    }

    // epilogue: raw dots store (finalize divides in a separate pass)
    #pragma unroll
    for (int mi = 0; mi < 4; ++mi) {
        #pragma unroll
        for (int ni = 0; ni < 8; ++ni) {
            int row = m0 + mb + mi * 16 + grp;
            int col = n0 + nb + ni * 8 + 2 * tig;
            *reinterpret_cast<float2*>(out + (size_t)row * NDIM + col) =
                make_float2(d[mi][ni][0], d[mi][ni][1]);
            *reinterpret_cast<float2*>(out + (size_t)(row + 8) * NDIM + col) =
                make_float2(d[mi][ni][2], d[mi][ni][3]);
        }
    }
}

// ===== kernel 3: finalize. s_i row-local: s^2 = sum_j dots_ij * x_ij =======

__global__ __launch_bounds__(256)
void finalize_kernel(const float* __restrict__ x, float* __restrict__ out)
{
    __shared__ float red[8];
    const int m = blockIdx.x, t = threadIdx.x, lane = t & 31;
    float4* dp = reinterpret_cast<float4*>(out + (size_t)m * NDIM);
    const float4* xp = reinterpret_cast<const float4*>(x + (size_t)m * NDIM);
    float4 dv = dp[t];
    float4 xv = xp[t];
    float a = dv.x * xv.x + dv.y * xv.y + dv.z * xv.z + dv.w * xv.w;
    #pragma unroll
    for (int o = 16; o > 0; o >>= 1) a += __shfl_xor_sync(0xffffffffu, a, o);
    if (lane == 0) red[t >> 5] = a;
    __syncthreads();
    float s2 = red[0] + red[1] + red[2] + red[3] + red[4] + red[5] + red[6] + red[7];
    float s = sqrtf(fmaxf(s2, 0.f));
    float4 ev = reinterpret_cast<const float4*>(e_norm)[t];
    dv.x = __fdividef(dv.x, fmaxf(s * ev.x, 1e-8f));
    dv.y = __fdividef(dv.y, fmaxf(s * ev.y, 1e-8f));
    dv.z = __fdividef(dv.z, fmaxf(s * ev.z, 1e-8f));
    dv.w = __fdividef(dv.w, fmaxf(s * ev.w, 1e-8f));
    dp[t] = dv;
}

// ============================== launch =====================================

extern "C" void kernel_launch(void* const* d_in, const int* in_sizes, int n_in,
                              void* d_out, int out_size) {
    const float* x   = (const float*)d_in[0];   // [1, 65536, 1024] fp32
    const float* emb = (const float*)d_in[1];   // [1024, 1024] fp32
    float* out = (float*)d_out;                 // [1, 65536, 1024] fp32
    (void)in_sizes; (void)n_in; (void)out_size;

    cudaFuncSetAttribute(main_gemm_kernel,
                         cudaFuncAttributeMaxDynamicSharedMemorySize, SMEM_MAIN);

    // 1) G = emb @ emb^T (tf32-rounded)
    g_gemm_kernel<<<dim3(NDIM / GBN, NDIM / GBM), 256>>>(emb);
    // 2) e_j = sqrt(G[j,j])
    diag_norm_kernel<<<NDIM / 256, 256>>>();
    // 3) dots = x @ G
    main_gemm_kernel<<<dim3(NDIM / BN, MDIM / BM), NTHREADS, SMEM_MAIN>>>(x, out);
    // 4) out = dots / max(s_i * e_j, eps)
    finalize_kernel<<<MDIM, 256>>>(x, out);
}

// round 6
// speedup vs baseline: 2.1061x; 2.1061x over previous
#include <cuda_runtime.h>
#include <cstdint>
#include <math.h>

// ---------------------------------------------------------------------------
// SoftEmbRescore (sm_100 base ISA — tcgen05 unavailable in this build):
//   G    = emb @ emb^T        (tf32 mma.sync, 1024x1024, tf32-rounded store)
//   dots = x @ G              (tf32 mma.sync, 128x256x32 CTA tiles, 64x64/warp)
//   out[i,j] = dots[i,j] / max(s_i * e_j, 1e-8)
//     e_j = sqrt(G[j,j]);  s_i = sqrt(sum_j dots[i,j]*x[i,j])   (row-local)
// 256 threads/CTA (NOT 512: 512thr@1CTA/SM caps regs at 128 = accum count,
// which spilled in R5 and caused the 2x regression).
// ---------------------------------------------------------------------------

namespace {
constexpr int MDIM = 65536;
constexpr int NDIM = 1024;
constexpr int KDIM = 1024;

// ---- main GEMM tiling ----
constexpr int BM = 128;
constexpr int BN = 256;
constexpr int BK = 32;
constexpr int LDSS = BK + 4;                    // 36: bank = 4*grp+tig, conflict-free
constexpr int NTHREADS = 256;
constexpr int NSTAGE = 3;
constexpr int NT = KDIM / BK;                   // 32
constexpr int STAGE_FLOATS = (BM + BN) * LDSS;  // 13824 floats = 55296 B
constexpr int SMEM_MAIN = NSTAGE * STAGE_FLOATS * 4;  // 165888 B (dynamic)

// ---- G-builder tiling (64 CTAs, ~20us) ----
constexpr int GBM = 128, GBN = 128, GBK = 16;
constexpr int GLDS = GBK + 4;
constexpr int GNT = KDIM / GBK;
constexpr int GSTAGE = (GBM + GBN) * GLDS;
}

__device__ __align__(16) float g_mat[(size_t)NDIM * NDIM];   // 4 MB (tf32-rounded)
__device__ __align__(16) float e_norm[NDIM];

// ============================ helpers ======================================

__device__ __forceinline__ uint32_t smem_u32(const void* p) {
    uint32_t a;
    asm("{ .reg .u64 t; cvta.to.shared.u64 t, %1; cvt.u32.u64 %0, t; }" : "=r"(a) : "l"(p));
    return a;
}
__device__ __forceinline__ uint32_t f2tf32(float f) {
    uint32_t r;
    asm("cvt.rna.tf32.f32 %0, %1;" : "=r"(r) : "f"(f));
    return r;
}
__device__ __forceinline__ void mma_tf32(float* d, const uint32_t* a, const uint32_t* b) {
    asm volatile(
        "mma.sync.aligned.m16n8k8.row.col.f32.tf32.tf32.f32 "
        "{%0,%1,%2,%3}, {%4,%5,%6,%7}, {%8,%9}, {%0,%1,%2,%3};"
        : "+f"(d[0]), "+f"(d[1]), "+f"(d[2]), "+f"(d[3])
        : "r"(a[0]), "r"(a[1]), "r"(a[2]), "r"(a[3]), "r"(b[0]), "r"(b[1]));
}

#define CP_ASYNC16(dst, src) \
    asm volatile("cp.async.cg.shared.global [%0], [%1], 16;" :: "r"(dst), "l"(src))
#define CP_COMMIT() asm volatile("cp.async.commit_group;")
#define CP_WAIT2()  asm volatile("cp.async.wait_group 2;")
#define CP_WAIT1()  asm volatile("cp.async.wait_group 1;")
#define CP_WAIT0()  asm volatile("cp.async.wait_group 0;")

// ============== kernel 1: G = emb @ emb^T (tf32-rounded store) =============

__global__ __launch_bounds__(256, 2)
void g_gemm_kernel(const float* __restrict__ A)
{
    __shared__ __align__(16) float smem[2 * GSTAGE];
    const int tid = threadIdx.x;
    const int m0 = blockIdx.y * GBM;
    const int n0 = blockIdx.x * GBN;

    auto load_stage = [&](int s, int kt) {
        const float* Ag = A + (size_t)m0 * KDIM + kt * GBK;
        const float* Bg = A + (size_t)n0 * KDIM + kt * GBK;
        float* Asm = smem + s * GSTAGE;
        float* Bsm = Asm + GBM * GLDS;
        #pragma unroll
        for (int i = 0; i < 2; ++i) {
            int chunk = tid + i * 256;
            int r = chunk >> 2;
            int c = (chunk & 3) * 4;
            CP_ASYNC16(smem_u32(Asm + r * GLDS + c), Ag + (size_t)r * KDIM + c);
            CP_ASYNC16(smem_u32(Bsm + r * GLDS + c), Bg + (size_t)r * KDIM + c);
        }
        CP_COMMIT();
    };

    const int warp = tid >> 5, lane = tid & 31;
    const int mb = (warp & 3) * 32, nb = (warp >> 2) * 64;
    const int grp = lane >> 2, tig = lane & 3;

    float d[2][8][4];
    #pragma unroll
    for (int mi = 0; mi < 2; ++mi)
        #pragma unroll
        for (int ni = 0; ni < 8; ++ni)
            #pragma unroll
            for (int r = 0; r < 4; ++r) d[mi][ni][r] = 0.f;

    load_stage(0, 0);
    for (int t = 0; t < GNT; ++t) {
        if (t + 1 < GNT) { load_stage((t + 1) & 1, t + 1); CP_WAIT1(); }
        else             { CP_WAIT0(); }
        __syncthreads();
        const float* Asm = smem + (t & 1) * GSTAGE;
        const float* Bsm = Asm + GBM * GLDS;
        #pragma unroll
        for (int kk = 0; kk < GBK; kk += 8) {
            uint32_t a[2][4];
            #pragma unroll
            for (int mi = 0; mi < 2; ++mi) {
                const float* p = Asm + (mb + mi * 16 + grp) * GLDS + kk + tig;
                a[mi][0] = f2tf32(p[0]);
                a[mi][1] = f2tf32(p[8 * GLDS]);
                a[mi][2] = f2tf32(p[4]);
                a[mi][3] = f2tf32(p[8 * GLDS + 4]);
            }
            uint32_t b[8][2];
            #pragma unroll
            for (int ni = 0; ni < 8; ++ni) {
                const float* p = Bsm + (nb + ni * 8 + grp) * GLDS + kk + tig;
                b[ni][0] = f2tf32(p[0]);
                b[ni][1] = f2tf32(p[4]);
            }
            #pragma unroll
            for (int mi = 0; mi < 2; ++mi)
                #pragma unroll
                for (int ni = 0; ni < 8; ++ni)
                    mma_tf32(d[mi][ni], a[mi], b[ni]);
        }
        __syncthreads();
    }
    #pragma unroll
    for (int mi = 0; mi < 2; ++mi) {
        #pragma unroll
        for (int ni = 0; ni < 8; ++ni) {
            int row = m0 + mb + mi * 16 + grp;
            int col = n0 + nb + ni * 8 + 2 * tig;
            g_mat[(size_t)row * NDIM + col]           = __uint_as_float(f2tf32(d[mi][ni][0]));
            g_mat[(size_t)row * NDIM + col + 1]       = __uint_as_float(f2tf32(d[mi][ni][1]));
            g_mat[(size_t)(row + 8) * NDIM + col]     = __uint_as_float(f2tf32(d[mi][ni][2]));
            g_mat[(size_t)(row + 8) * NDIM + col + 1] = __uint_as_float(f2tf32(d[mi][ni][3]));
        }
    }
}

__global__ void diag_norm_kernel() {
    int j = blockIdx.x * blockDim.x + threadIdx.x;
    if (j < NDIM) e_norm[j] = sqrtf(fmaxf(g_mat[(size_t)j * NDIM + j], 0.f));
}

// ====== kernel 2: dots = x @ G, 128x256 CTA, 64x64/warp, 256 threads =======

__global__ __launch_bounds__(NTHREADS, 1)
void main_gemm_kernel(const float* __restrict__ x, float* __restrict__ out)
{
    extern __shared__ __align__(16) float smem[];
    const int tid = threadIdx.x;
    const int m0 = blockIdx.y * BM;
    const int n0 = blockIdx.x * BN;

    auto fill = [&](int kt) {
        float* S = smem + (kt % NSTAGE) * STAGE_FLOATS;
        const float* Ag = x + (size_t)m0 * KDIM + kt * BK;
        const float* Bg = g_mat + (size_t)n0 * KDIM + kt * BK;
        #pragma unroll
        for (int i = 0; i < 12; ++i) {
            int chunk = tid + i * NTHREADS;       // 0..3071
            int r = chunk >> 3;                   // 0..383 (A rows 0-127, B 128-383)
            int c = (chunk & 7) * 4;              // 0,4,...,28
            const float* src = (r < BM) ? (Ag + (size_t)r * KDIM + c)
                                        : (Bg + (size_t)(r - BM) * KDIM + c);
            CP_ASYNC16(smem_u32(S + r * LDSS + c), src);
        }
        CP_COMMIT();
    };

    const int warp = tid >> 5, lane = tid & 31;
    const int mb = (warp & 1) * 64;               // 2 warps along M
    const int nb = (warp >> 1) * 64;              // 4 warps along N
    const int grp = lane >> 2, tig = lane & 3;

    float d[4][8][4];
    #pragma unroll
    for (int mi = 0; mi < 4; ++mi)
        #pragma unroll
        for (int ni = 0; ni < 8; ++ni)
            #pragma unroll
            for (int r = 0; r < 4; ++r) d[mi][ni][r] = 0.f;

    // prologue: stages 0,1
    fill(0); fill(1);

    for (int t = 0; t < NT; ++t) {
        if (t + 2 < NT) fill(t + 2);
        else            CP_COMMIT();              // keep group count fixed
        CP_WAIT2();                               // group t complete
        __syncthreads();

        const float* Asm = smem + (t % NSTAGE) * STAGE_FLOATS;
        const float* Bsm = Asm + BM * LDSS;

        #pragma unroll
        for (int kk = 0; kk < BK; kk += 8) {
            uint32_t a[4][4];
            #pragma unroll
            for (int mi = 0; mi < 4; ++mi) {
                const float* p = Asm + (mb + mi * 16 + grp) * LDSS + kk + tig;
                a[mi][0] = f2tf32(p[0]);
                a[mi][1] = f2tf32(p[8 * LDSS]);
                a[mi][2] = f2tf32(p[4]);
                a[mi][3] = f2tf32(p[8 * LDSS + 4]);
            }
            uint32_t b[8][2];
            #pragma unroll
            for (int ni = 0; ni < 8; ++ni) {
                const float* p = Bsm + (nb + ni * 8 + grp) * LDSS + kk + tig;
                b[ni][0] = __float_as_uint(p[0]);   // g_mat pre-rounded to tf32
                b[ni][1] = __float_as_uint(p[4]);
            }
            #pragma unroll
            for (int mi = 0; mi < 4; ++mi)
                #pragma unroll
                for (int ni = 0; ni < 8; ++ni)
                    mma_tf32(d[mi][ni], a[mi], b[ni]);
        }
        __syncthreads();                          // all warps done with buf t
    }

    // epilogue: raw dots (finalize divides in a separate pass)
    #pragma unroll
    for (int mi = 0; mi < 4; ++mi) {
        #pragma unroll
        for (int ni = 0; ni < 8; ++ni) {
            int row = m0 + mb + mi * 16 + grp;
            int col = n0 + nb + ni * 8 + 2 * tig;
            *reinterpret_cast<float2*>(out + (size_t)row * NDIM + col) =
                make_float2(d[mi][ni][0], d[mi][ni][1]);
            *reinterpret_cast<float2*>(out + (size_t)(row + 8) * NDIM + col) =
                make_float2(d[mi][ni][2], d[mi][ni][3]);
        }
    }
}

// ===== kernel 3: finalize. s_i row-local: s^2 = sum_j dots_ij * x_ij =======

__global__ __launch_bounds__(256)
void finalize_kernel(const float* __restrict__ x, float* __restrict__ out)
{
    __shared__ float red[8];
    const int m = blockIdx.x, t = threadIdx.x, lane = t & 31;
    float4* dp = reinterpret_cast<float4*>(out + (size_t)m * NDIM);
    const float4* xp = reinterpret_cast<const float4*>(x + (size_t)m * NDIM);
    float4 dv = dp[t];
    float4 xv = xp[t];
    float a = dv.x * xv.x + dv.y * xv.y + dv.z * xv.z + dv.w * xv.w;
    #pragma unroll
    for (int o = 16; o > 0; o >>= 1) a += __shfl_xor_sync(0xffffffffu, a, o);
    if (lane == 0) red[t >> 5] = a;
    __syncthreads();
    float s2 = red[0] + red[1] + red[2] + red[3] + red[4] + red[5] + red[6] + red[7];
    float s = sqrtf(fmaxf(s2, 0.f));
    float4 ev = reinterpret_cast<const float4*>(e_norm)[t];
    dv.x = __fdividef(dv.x, fmaxf(s * ev.x, 1e-8f));
    dv.y = __fdividef(dv.y, fmaxf(s * ev.y, 1e-8f));
    dv.z = __fdividef(dv.z, fmaxf(s * ev.z, 1e-8f));
    dv.w = __fdividef(dv.w, fmaxf(s * ev.w, 1e-8f));
    dp[t] = dv;
}

// ============================== launch =====================================

extern "C" void kernel_launch(void* const* d_in, const int* in_sizes, int n_in,
                              void* d_out, int out_size) {
    const float* x   = (const float*)d_in[0];   // [1, 65536, 1024] fp32
    const float* emb = (const float*)d_in[1];   // [1024, 1024] fp32
    float* out = (float*)d_out;                 // [1, 65536, 1024] fp32
    (void)in_sizes; (void)n_in; (void)out_size;

    cudaFuncSetAttribute(main_gemm_kernel,
                         cudaFuncAttributeMaxDynamicSharedMemorySize, SMEM_MAIN);

    // 1) G = emb @ emb^T (tf32-rounded)
    g_gemm_kernel<<<dim3(NDIM / GBN, NDIM / GBM), 256>>>(emb);
    // 2) e_j = sqrt(G[j,j])
    diag_norm_kernel<<<NDIM / 256, 256>>>();
    // 3) dots = x @ G
    main_gemm_kernel<<<dim3(NDIM / BN, MDIM / BM), NTHREADS, SMEM_MAIN>>>(x, out);
    // 4) out = dots / max(s_i * e_j, eps)
    finalize_kernel<<<MDIM, 256>>>(x, out);
}

// round 7
// speedup vs baseline: 3.3615x; 1.5960x over previous
#include <cuda_runtime.h>
#include <cuda_fp16.h>
#include <cstdint>
#include <math.h>

// ---------------------------------------------------------------------------
// SoftEmbRescore (sm_100 base ISA — tcgen05 unavailable in this build):
//   G    = emb @ emb^T      (tf32 mma.sync, 1024x1024, stored as fp16)
//   x_h  = fp16(x)          (pre-pass, 128 MB scratch)
//   dots = x_h @ G_h        (fp16 m16n8k16 mma.sync — 2x tf32 MAC rate,
//                            SAME 11-bit significand as tf32)
//   out[i,j] = dots[i,j] / max(s_i * e_j, 1e-8)
//     e_j = sqrt(G[j,j]);  s_i = sqrt(sum_j dots[i,j]*x[i,j])   (row-local)
// ---------------------------------------------------------------------------

namespace {
constexpr int MDIM = 65536;
constexpr int NDIM = 1024;
constexpr int KDIM = 1024;

// ---- main GEMM tiling (fp16) ----
constexpr int BM = 128;
constexpr int BN = 256;
constexpr int BK = 64;                           // halves; 128 B rows
constexpr int LDSH = BK + 8;                     // 72 halves = 144 B rows
constexpr int NTHREADS = 256;
constexpr int NSTAGE = 3;
constexpr int NT = KDIM / BK;                    // 16
constexpr int STAGE_HALVES = (BM + BN) * LDSH;   // 27648 halves = 55296 B
constexpr int SMEM_MAIN = NSTAGE * STAGE_HALVES * 2;  // 165888 B

// ---- G-builder tiling (tf32 mma.sync, 64 CTAs) ----
constexpr int GBM = 128, GBN = 128, GBK = 16;
constexpr int GLDS = GBK + 4;
constexpr int GNT = KDIM / GBK;
constexpr int GSTAGE = (GBM + GBN) * GLDS;
}

__device__ __align__(16) __half g_h[(size_t)NDIM * NDIM];     // 2 MB
__device__ __align__(16) __half x_h[(size_t)MDIM * KDIM];     // 128 MB
__device__ __align__(16) float e_norm[NDIM];

// ============================ helpers ======================================

__device__ __forceinline__ uint32_t smem_u32(const void* p) {
    uint32_t a;
    asm("{ .reg .u64 t; cvta.to.shared.u64 t, %1; cvt.u32.u64 %0, t; }" : "=r"(a) : "l"(p));
    return a;
}
__device__ __forceinline__ uint32_t f2tf32(float f) {
    uint32_t r;
    asm("cvt.rna.tf32.f32 %0, %1;" : "=r"(r) : "f"(f));
    return r;
}
__device__ __forceinline__ void mma_tf32(float* d, const uint32_t* a, const uint32_t* b) {
    asm volatile(
        "mma.sync.aligned.m16n8k8.row.col.f32.tf32.tf32.f32 "
        "{%0,%1,%2,%3}, {%4,%5,%6,%7}, {%8,%9}, {%0,%1,%2,%3};"
        : "+f"(d[0]), "+f"(d[1]), "+f"(d[2]), "+f"(d[3])
        : "r"(a[0]), "r"(a[1]), "r"(a[2]), "r"(a[3]), "r"(b[0]), "r"(b[1]));
}
__device__ __forceinline__ void mma_f16(float* d, const uint32_t* a, const uint32_t* b) {
    asm volatile(
        "mma.sync.aligned.m16n8k16.row.col.f32.f16.f16.f32 "
        "{%0,%1,%2,%3}, {%4,%5,%6,%7}, {%8,%9}, {%0,%1,%2,%3};"
        : "+f"(d[0]), "+f"(d[1]), "+f"(d[2]), "+f"(d[3])
        : "r"(a[0]), "r"(a[1]), "r"(a[2]), "r"(a[3]), "r"(b[0]), "r"(b[1]));
}

#define CP_ASYNC16(dst, src) \
    asm volatile("cp.async.cg.shared.global [%0], [%1], 16;" :: "r"(dst), "l"(src))
#define CP_COMMIT() asm volatile("cp.async.commit_group;")
#define CP_WAIT2()  asm volatile("cp.async.wait_group 2;")
#define CP_WAIT1()  asm volatile("cp.async.wait_group 1;")
#define CP_WAIT0()  asm volatile("cp.async.wait_group 0;")

// ================= kernel 0: x -> fp16 (8 elems/thread) ====================

__global__ __launch_bounds__(256) void cvt_x_kernel(const float* __restrict__ x) {
    size_t i = ((size_t)blockIdx.x * 256 + threadIdx.x) * 8;
    float4 v0 = *reinterpret_cast<const float4*>(x + i);
    float4 v1 = *reinterpret_cast<const float4*>(x + i + 4);
    __half2 h[4];
    h[0] = __floats2half2_rn(v0.x, v0.y);
    h[1] = __floats2half2_rn(v0.z, v0.w);
    h[2] = __floats2half2_rn(v1.x, v1.y);
    h[3] = __floats2half2_rn(v1.z, v1.w);
    *reinterpret_cast<uint4*>(x_h + i) = *reinterpret_cast<uint4*>(h);
}

// ========= kernel 1: G = emb @ emb^T (tf32 compute, fp16 store) ============

__global__ __launch_bounds__(256, 2)
void g_gemm_kernel(const float* __restrict__ A)
{
    __shared__ __align__(16) float smem[2 * GSTAGE];
    const int tid = threadIdx.x;
    const int m0 = blockIdx.y * GBM;
    const int n0 = blockIdx.x * GBN;

    auto load_stage = [&](int s, int kt) {
        const float* Ag = A + (size_t)m0 * KDIM + kt * GBK;
        const float* Bg = A + (size_t)n0 * KDIM + kt * GBK;
        float* Asm = smem + s * GSTAGE;
        float* Bsm = Asm + GBM * GLDS;
        #pragma unroll
        for (int i = 0; i < 2; ++i) {
            int chunk = tid + i * 256;
            int r = chunk >> 2;
            int c = (chunk & 3) * 4;
            CP_ASYNC16(smem_u32(Asm + r * GLDS + c), Ag + (size_t)r * KDIM + c);
            CP_ASYNC16(smem_u32(Bsm + r * GLDS + c), Bg + (size_t)r * KDIM + c);
        }
        CP_COMMIT();
    };

    const int warp = tid >> 5, lane = tid & 31;
    const int mb = (warp & 3) * 32, nb = (warp >> 2) * 64;
    const int grp = lane >> 2, tig = lane & 3;

    float d[2][8][4];
    #pragma unroll
    for (int mi = 0; mi < 2; ++mi)
        #pragma unroll
        for (int ni = 0; ni < 8; ++ni)
            #pragma unroll
            for (int r = 0; r < 4; ++r) d[mi][ni][r] = 0.f;

    load_stage(0, 0);
    for (int t = 0; t < GNT; ++t) {
        if (t + 1 < GNT) { load_stage((t + 1) & 1, t + 1); CP_WAIT1(); }
        else             { CP_WAIT0(); }
        __syncthreads();
        const float* Asm = smem + (t & 1) * GSTAGE;
        const float* Bsm = Asm + GBM * GLDS;
        #pragma unroll
        for (int kk = 0; kk < GBK; kk += 8) {
            uint32_t a[2][4];
            #pragma unroll
            for (int mi = 0; mi < 2; ++mi) {
                const float* p = Asm + (mb + mi * 16 + grp) * GLDS + kk + tig;
                a[mi][0] = f2tf32(p[0]);
                a[mi][1] = f2tf32(p[8 * GLDS]);
                a[mi][2] = f2tf32(p[4]);
                a[mi][3] = f2tf32(p[8 * GLDS + 4]);
            }
            uint32_t b[8][2];
            #pragma unroll
            for (int ni = 0; ni < 8; ++ni) {
                const float* p = Bsm + (nb + ni * 8 + grp) * GLDS + kk + tig;
                b[ni][0] = f2tf32(p[0]);
                b[ni][1] = f2tf32(p[4]);
            }
            #pragma unroll
            for (int mi = 0; mi < 2; ++mi)
                #pragma unroll
                for (int ni = 0; ni < 8; ++ni)
                    mma_tf32(d[mi][ni], a[mi], b[ni]);
        }
        __syncthreads();
    }
    // store G as fp16 (the exact operand the main GEMM consumes)
    #pragma unroll
    for (int mi = 0; mi < 2; ++mi) {
        #pragma unroll
        for (int ni = 0; ni < 8; ++ni) {
            int row = m0 + mb + mi * 16 + grp;
            int col = n0 + nb + ni * 8 + 2 * tig;
            *reinterpret_cast<__half2*>(g_h + (size_t)row * NDIM + col) =
                __floats2half2_rn(d[mi][ni][0], d[mi][ni][1]);
            *reinterpret_cast<__half2*>(g_h + (size_t)(row + 8) * NDIM + col) =
                __floats2half2_rn(d[mi][ni][2], d[mi][ni][3]);
        }
    }
}

__global__ void diag_norm_kernel() {
    int j = blockIdx.x * blockDim.x + threadIdx.x;
    if (j < NDIM)
        e_norm[j] = sqrtf(fmaxf(__half2float(g_h[(size_t)j * NDIM + j]), 0.f));
}

// ==== kernel 2: dots = x_h @ G_h, fp16 m16n8k16, 128x256 CTA, 64x64/warp ===

__global__ __launch_bounds__(NTHREADS, 1)
void main_gemm_kernel(float* __restrict__ out)
{
    extern __shared__ __align__(16) __half smem_h[];
    const int tid = threadIdx.x;
    const int m0 = blockIdx.y * BM;
    const int n0 = blockIdx.x * BN;

    auto fill = [&](int kt) {
        __half* S = smem_h + (kt % NSTAGE) * STAGE_HALVES;
        const __half* Ag = x_h + (size_t)m0 * KDIM + kt * BK;
        const __half* Bg = g_h + (size_t)n0 * KDIM + kt * BK;
        #pragma unroll
        for (int i = 0; i < 12; ++i) {
            int chunk = tid + i * NTHREADS;       // 0..3071 (16B chunks)
            int r = chunk >> 3;                   // 0..383 (A 0-127, B 128-383)
            int c = (chunk & 7) * 8;              // halves: 0,8,...,56
            const __half* src = (r < BM) ? (Ag + (size_t)r * KDIM + c)
                                         : (Bg + (size_t)(r - BM) * KDIM + c);
            CP_ASYNC16(smem_u32(S + r * LDSH + c), src);
        }
        CP_COMMIT();
    };

    const int warp = tid >> 5, lane = tid & 31;
    const int mb = (warp & 1) * 64;               // 2 warps along M
    const int nb = (warp >> 1) * 64;              // 4 warps along N
    const int grp = lane >> 2, tig = lane & 3;

    float d[4][8][4];
    #pragma unroll
    for (int mi = 0; mi < 4; ++mi)
        #pragma unroll
        for (int ni = 0; ni < 8; ++ni)
            #pragma unroll
            for (int r = 0; r < 4; ++r) d[mi][ni][r] = 0.f;

    fill(0); fill(1);

    for (int t = 0; t < NT; ++t) {
        if (t + 2 < NT) fill(t + 2);
        else            CP_COMMIT();              // fixed group accounting
        CP_WAIT2();
        __syncthreads();

        const __half* Asm = smem_h + (t % NSTAGE) * STAGE_HALVES;
        const __half* Bsm = Asm + BM * LDSH;

        #pragma unroll
        for (int kk = 0; kk < BK; kk += 16) {
            // A fragment (m16n8k16): a0 = (row grp, k 2t..2t+1), a1 = row+8,
            // a2 = k+8, a3 = row+8 & k+8. Consecutive half pairs -> b32 loads.
            uint32_t a[4][4];
            #pragma unroll
            for (int mi = 0; mi < 4; ++mi) {
                const __half* p = Asm + (mb + mi * 16 + grp) * LDSH + kk + 2 * tig;
                a[mi][0] = *reinterpret_cast<const uint32_t*>(p);
                a[mi][1] = *reinterpret_cast<const uint32_t*>(p + 8 * LDSH);
                a[mi][2] = *reinterpret_cast<const uint32_t*>(p + 8);
                a[mi][3] = *reinterpret_cast<const uint32_t*>(p + 8 * LDSH + 8);
            }
            // B fragment: b0 = (n grp, k 2t..2t+1), b1 = k+8.
            uint32_t b[8][2];
            #pragma unroll
            for (int ni = 0; ni < 8; ++ni) {
                const __half* q = Bsm + (nb + ni * 8 + grp) * LDSH + kk + 2 * tig;
                b[ni][0] = *reinterpret_cast<const uint32_t*>(q);
                b[ni][1] = *reinterpret_cast<const uint32_t*>(q + 8);
            }
            #pragma unroll
            for (int mi = 0; mi < 4; ++mi)
                #pragma unroll
                for (int ni = 0; ni < 8; ++ni)
                    mma_f16(d[mi][ni], a[mi], b[ni]);
        }
        __syncthreads();
    }

    // epilogue: raw dots (finalize divides in a separate pass)
    #pragma unroll
    for (int mi = 0; mi < 4; ++mi) {
        #pragma unroll
        for (int ni = 0; ni < 8; ++ni) {
            int row = m0 + mb + mi * 16 + grp;
            int col = n0 + nb + ni * 8 + 2 * tig;
            *reinterpret_cast<float2*>(out + (size_t)row * NDIM + col) =
                make_float2(d[mi][ni][0], d[mi][ni][1]);
            *reinterpret_cast<float2*>(out + (size_t)(row + 8) * NDIM + col) =
                make_float2(d[mi][ni][2], d[mi][ni][3]);
        }
    }
}

// ===== kernel 3: finalize. s_i row-local: s^2 = sum_j dots_ij * x_ij =======

__global__ __launch_bounds__(256)
void finalize_kernel(float* __restrict__ out)
{
    __shared__ float red[8];
    const int m = blockIdx.x, t = threadIdx.x, lane = t & 31;
    float4* dp = reinterpret_cast<float4*>(out + (size_t)m * NDIM);
    float4 dv = dp[t];
    uint2 xr = *reinterpret_cast<const uint2*>(x_h + (size_t)m * NDIM + t * 4);
    float2 x01 = __half22float2(*reinterpret_cast<__half2*>(&xr.x));
    float2 x23 = __half22float2(*reinterpret_cast<__half2*>(&xr.y));
    float a = dv.x * x01.x + dv.y * x01.y + dv.z * x23.x + dv.w * x23.y;
    #pragma unroll
    for (int o = 16; o > 0; o >>= 1) a += __shfl_xor_sync(0xffffffffu, a, o);
    if (lane == 0) red[t >> 5] = a;
    __syncthreads();
    float s2 = red[0] + red[1] + red[2] + red[3] + red[4] + red[5] + red[6] + red[7];
    float s = sqrtf(fmaxf(s2, 0.f));
    float4 ev = reinterpret_cast<const float4*>(e_norm)[t];
    dv.x = __fdividef(dv.x, fmaxf(s * ev.x, 1e-8f));
    dv.y = __fdividef(dv.y, fmaxf(s * ev.y, 1e-8f));
    dv.z = __fdividef(dv.z, fmaxf(s * ev.z, 1e-8f));
    dv.w = __fdividef(dv.w, fmaxf(s * ev.w, 1e-8f));
    dp[t] = dv;
}

// ============================== launch =====================================

extern "C" void kernel_launch(void* const* d_in, const int* in_sizes, int n_in,
                              void* d_out, int out_size) {
    const float* x   = (const float*)d_in[0];   // [1, 65536, 1024] fp32
    const float* emb = (const float*)d_in[1];   // [1024, 1024] fp32
    float* out = (float*)d_out;                 // [1, 65536, 1024] fp32
    (void)in_sizes; (void)n_in; (void)out_size;

    cudaFuncSetAttribute(main_gemm_kernel,
                         cudaFuncAttributeMaxDynamicSharedMemorySize, SMEM_MAIN);

    // 0) x_h = fp16(x)
    cvt_x_kernel<<<(int)((size_t)MDIM * KDIM / 2048), 256>>>(x);
    // 1) G = emb @ emb^T (tf32 compute, fp16 store)
    g_gemm_kernel<<<dim3(NDIM / GBN, NDIM / GBM), 256>>>(emb);
    // 2) e_j = sqrt(G[j,j])
    diag_norm_kernel<<<NDIM / 256, 256>>>();
    // 3) dots = x_h @ G_h  (fp16 tensor cores)
    main_gemm_kernel<<<dim3(NDIM / BN, MDIM / BM), NTHREADS, SMEM_MAIN>>>(out);
    // 4) out = dots / max(s_i * e_j, eps)
    finalize_kernel<<<MDIM, 256>>>(out);
}